// round 1
// baseline (speedup 1.0000x reference)
#include <cuda_runtime.h>

// ---------------- problem constants (fixed shapes) ----------------
#define NMAX   100000
#define FDIM   128
#define HDIM   128
#define EDIM   64
#define RREL   3
#define TMAXC  2048      // max unique targets (2*B)
#define S1MAX  49152     // max |S1| (expected ~30K)
#define E2MAX  131072    // max layer-2 edges (expected ~33K)

// ---------------- device scratch (static, no allocation) ----------------
__device__ int   g_tid[NMAX];       // node -> target compact id (-1 none)
__device__ int   g_s1id[NMAX];      // node -> S1 compact id (-1 none)
__device__ int   g_tnodes[TMAXC];
__device__ int   g_t2s1[TMAXC];     // target idx -> s1 idx
__device__ int   g_s1nodes[S1MAX];
__device__ int   g_tcount;
__device__ int   g_s1count;
__device__ int   g_e2count;
__device__ int   g_e2src[E2MAX];
__device__ int   g_e2bin[E2MAX];
__device__ float g_agg1[(size_t)RREL * S1MAX * FDIM];   // ~75.5 MB
__device__ int   g_cnt1[RREL * S1MAX];
__device__ float g_inv1[RREL * S1MAX];
__device__ float g_h1[(size_t)S1MAX * HDIM];            // ~25 MB
__device__ float g_agg2[RREL * TMAXC * HDIM];
__device__ int   g_cnt2[RREL * TMAXC];
__device__ float g_inv2[RREL * TMAXC];
__device__ float g_node[TMAXC * EDIM];

__device__ __forceinline__ void red_add_v4(float* p, float4 v) {
    asm volatile("red.global.add.v4.f32 [%0], {%1,%2,%3,%4};"
                 :: "l"(p), "f"(v.x), "f"(v.y), "f"(v.z), "f"(v.w) : "memory");
}

// ---------------- k0: init maps/counters ----------------
__global__ void k0_init(int N) {
    int i = blockIdx.x * blockDim.x + threadIdx.x;
    int stride = gridDim.x * blockDim.x;
    for (int j = i; j < N; j += stride) { g_tid[j] = -1; g_s1id[j] = -1; }
    for (int j = i; j < RREL * S1MAX; j += stride) g_cnt1[j] = 0;
    for (int j = i; j < RREL * TMAXC; j += stride) g_cnt2[j] = 0;
    for (int j = i; j < RREL * TMAXC * HDIM; j += stride) g_agg2[j] = 0.f;
    if (i == 0) { g_tcount = 0; g_s1count = 0; g_e2count = 0; }
}

// ---------------- k1: mark target set T = nest ∪ food ----------------
__global__ void k1_targets(const int* __restrict__ nest,
                           const int* __restrict__ food, int B) {
    int i = blockIdx.x * blockDim.x + threadIdx.x;
    if (i >= 2 * B) return;
    int v = (i < B) ? nest[i] : food[i - B];
    if (atomicCAS(&g_tid[v], -1, -2) == -1) {
        int id = atomicAdd(&g_tcount, 1);       // <= 2*B <= TMAXC
        g_tnodes[id] = v;
        // also claim into S1 (targets need h1 for root term)
        int sid = atomicAdd(&g_s1count, 1);
        g_s1nodes[sid] = v;
        g_s1id[v] = sid;
        g_t2s1[id] = sid;
        g_tid[v] = id;
    }
}

// ---------------- k2: scan edges, keep dst∈T, build S1 ----------------
__global__ void k2_scan(const int* __restrict__ esrc, const int* __restrict__ edst,
                        const int* __restrict__ etyp, int E) {
    int e = blockIdx.x * blockDim.x + threadIdx.x;
    bool pass = false;
    int td = -1;
    if (e < E) {
        td = g_tid[edst[e]];
        pass = (td >= 0);
    }
    unsigned mask = __ballot_sync(0xffffffffu, pass);
    if (!pass) return;
    int t = etyp[e];
    int s = esrc[e];
    int lane = threadIdx.x & 31;
    int leader = __ffs(mask) - 1;
    int rank = __popc(mask & ((1u << lane) - 1));
    int base = 0;
    if (lane == leader) base = atomicAdd(&g_e2count, __popc(mask));
    base = __shfl_sync(mask, base, leader);
    int idx = base + rank;
    int bin = t * TMAXC + td;
    atomicAdd(&g_cnt2[bin], 1);
    if (idx < E2MAX) { g_e2src[idx] = s; g_e2bin[idx] = bin; }
    if (atomicCAS(&g_s1id[s], -1, -2) == -1) {
        int id = atomicAdd(&g_s1count, 1);
        if (id < S1MAX) { g_s1nodes[id] = s; g_s1id[s] = id; }
    }
}

// ---------------- k3: zero exactly the used part of agg1 ----------------
__global__ void k3_zero() {
    int cnt = g_s1count; if (cnt > S1MAX) cnt = S1MAX;
    int per4 = cnt * (FDIM / 4);                // float4 count per relation
    int r = blockIdx.y;
    float4* base = (float4*)&g_agg1[(size_t)r * S1MAX * FDIM];
    float4 z = make_float4(0.f, 0.f, 0.f, 0.f);
    for (int j = blockIdx.x * blockDim.x + threadIdx.x; j < per4;
         j += gridDim.x * blockDim.x)
        base[j] = z;
}

// ---------------- k4: layer-1 edge aggregation (pre-matmul) ----------------
__global__ void k4_agg1(const int* __restrict__ esrc, const int* __restrict__ edst,
                        const int* __restrict__ etyp, const float* __restrict__ x,
                        int E) {
    int w = (blockIdx.x * blockDim.x + threadIdx.x) >> 5;
    int lane = threadIdx.x & 31;
    int nw = (gridDim.x * blockDim.x) >> 5;
    for (int e = w; e < E; e += nw) {
        int d = edst[e];
        int sid = g_s1id[d];
        if (sid < 0) continue;
        int t = etyp[e];
        int s = esrc[e];
        int bin = t * S1MAX + sid;
        if (lane == 0) atomicAdd(&g_cnt1[bin], 1);
        float4 v = *(const float4*)&x[s * FDIM + lane * 4];
        red_add_v4(&g_agg1[(size_t)bin * FDIM + lane * 4], v);
    }
}

// ---------------- k4b: reciprocal counts ----------------
__global__ void k4b_inv() {
    int i = blockIdx.x * blockDim.x + threadIdx.x;
    if (i < RREL * S1MAX) {
        int c = g_cnt1[i];
        g_inv1[i] = 1.0f / (float)(c > 1 ? c : 1);
    }
    int j = i - RREL * S1MAX;
    if (j >= 0 && j < RREL * TMAXC) {
        int c = g_cnt2[j];
        g_inv2[j] = 1.0f / (float)(c > 1 ? c : 1);
    }
}

// ---------------- k5: fused GEMM1: h1 = relu([agg1/c | x] @ [Wrel1;Wroot1] + b1)
// M = s1count (<=S1MAX), K = 512, N = 128. BM=64, BN=128, BK=16, 256 threads.
__global__ __launch_bounds__(256) void k5_gemm_h1(
    const float* __restrict__ x, const float* __restrict__ Wrel,
    const float* __restrict__ Wroot, const float* __restrict__ bias) {
    int M = g_s1count; if (M > S1MAX) M = S1MAX;
    int row0 = blockIdx.x * 64;
    if (row0 >= M) return;
    __shared__ float As[16][64];
    __shared__ float Bs[16][128];
    int tid = threadIdx.x;
    int rg = tid >> 5;          // warp id: rows rg*8..rg*8+7
    int cg = tid & 31;          // cols cg*4..cg*4+3
    float acc[8][4];
#pragma unroll
    for (int m = 0; m < 8; m++)
#pragma unroll
        for (int n = 0; n < 4; n++) acc[m][n] = 0.f;

    int a_i = tid >> 2;         // 0..63
    int a_kk = (tid & 3) * 4;   // 0,4,8,12
    int gi = row0 + a_i;
    int anode = (gi < M) ? g_s1nodes[gi] : 0;

    for (int kt = 0; kt < 32; kt++) {
        int k0 = kt * 16;
        float4 av = make_float4(0.f, 0.f, 0.f, 0.f);
        if (gi < M) {
            int k = k0 + a_kk;
            int seg = k >> 7;
            if (seg < 3) {
                av = *(const float4*)&g_agg1[((size_t)(seg * S1MAX + gi)) * FDIM + (k & 127)];
                float inv = g_inv1[seg * S1MAX + gi];
                av.x *= inv; av.y *= inv; av.z *= inv; av.w *= inv;
            } else {
                av = *(const float4*)&x[anode * FDIM + (k - 384)];
            }
        }
        As[a_kk + 0][a_i] = av.x;
        As[a_kk + 1][a_i] = av.y;
        As[a_kk + 2][a_i] = av.z;
        As[a_kk + 3][a_i] = av.w;
#pragma unroll
        for (int u = 0; u < 2; u++) {
            int j = tid + u * 256;
            int kk = j >> 5, col = (j & 31) * 4;
            int k = k0 + kk;
            const float* srcp = (k < 384) ? &Wrel[(size_t)k * HDIM + col]
                                          : &Wroot[(size_t)(k - 384) * HDIM + col];
            *(float4*)&Bs[kk][col] = *(const float4*)srcp;
        }
        __syncthreads();
#pragma unroll
        for (int kk = 0; kk < 16; kk++) {
            float a[8];
            float4 t0 = *(float4*)&As[kk][rg * 8];
            float4 t1 = *(float4*)&As[kk][rg * 8 + 4];
            a[0] = t0.x; a[1] = t0.y; a[2] = t0.z; a[3] = t0.w;
            a[4] = t1.x; a[5] = t1.y; a[6] = t1.z; a[7] = t1.w;
            float4 bb = *(float4*)&Bs[kk][cg * 4];
            float b4[4] = {bb.x, bb.y, bb.z, bb.w};
#pragma unroll
            for (int m = 0; m < 8; m++)
#pragma unroll
                for (int n = 0; n < 4; n++) acc[m][n] += a[m] * b4[n];
        }
        __syncthreads();
    }
    float4 bv = *(const float4*)&bias[cg * 4];
#pragma unroll
    for (int m = 0; m < 8; m++) {
        int row = row0 + rg * 8 + m;
        if (row < M) {
            float4 o;
            o.x = fmaxf(acc[m][0] + bv.x, 0.f);
            o.y = fmaxf(acc[m][1] + bv.y, 0.f);
            o.z = fmaxf(acc[m][2] + bv.z, 0.f);
            o.w = fmaxf(acc[m][3] + bv.w, 0.f);
            *(float4*)&g_h1[(size_t)row * HDIM + cg * 4] = o;
        }
    }
}

// ---------------- k6: layer-2 edge aggregation (pre-matmul, compacted edges) --
__global__ void k6_agg2() {
    int n2 = g_e2count; if (n2 > E2MAX) n2 = E2MAX;
    int w = (blockIdx.x * blockDim.x + threadIdx.x) >> 5;
    int lane = threadIdx.x & 31;
    int nw = (gridDim.x * blockDim.x) >> 5;
    for (int i = w; i < n2; i += nw) {
        int s = g_e2src[i];
        int bin = g_e2bin[i];
        int sid = g_s1id[s];
        if (sid < 0) continue;  // safety (shouldn't happen)
        float4 v = *(const float4*)&g_h1[(size_t)sid * HDIM + lane * 4];
        red_add_v4(&g_agg2[(size_t)bin * HDIM + lane * 4], v);
    }
}

// ---------------- k7: GEMM2: node = [agg2/c | h1_T] @ [Wrel2;Wroot2] + b2 ----
// M = tcount (<=TMAXC), K = 512, N = 64. BM=64, BN=64, BK=16, 256 threads.
__global__ __launch_bounds__(256) void k7_gemm_node(
    const float* __restrict__ Wrel, const float* __restrict__ Wroot,
    const float* __restrict__ bias) {
    int M = g_tcount; if (M > TMAXC) M = TMAXC;
    int row0 = blockIdx.x * 64;
    if (row0 >= M) return;
    __shared__ float As[16][64];
    __shared__ float Bs[16][64];
    int tid = threadIdx.x;
    int rg = tid >> 4;          // 0..15, rows rg*4..rg*4+3
    int cg = tid & 15;          // cols cg*4..cg*4+3
    float acc[4][4];
#pragma unroll
    for (int m = 0; m < 4; m++)
#pragma unroll
        for (int n = 0; n < 4; n++) acc[m][n] = 0.f;

    int a_i = tid >> 2;
    int a_kk = (tid & 3) * 4;
    int gi = row0 + a_i;
    int hsrc = (gi < M) ? g_t2s1[gi] : 0;

    for (int kt = 0; kt < 32; kt++) {
        int k0 = kt * 16;
        float4 av = make_float4(0.f, 0.f, 0.f, 0.f);
        if (gi < M) {
            int k = k0 + a_kk;
            int seg = k >> 7;
            if (seg < 3) {
                av = *(const float4*)&g_agg2[((size_t)(seg * TMAXC + gi)) * HDIM + (k & 127)];
                float inv = g_inv2[seg * TMAXC + gi];
                av.x *= inv; av.y *= inv; av.z *= inv; av.w *= inv;
            } else {
                av = *(const float4*)&g_h1[(size_t)hsrc * HDIM + (k - 384)];
            }
        }
        As[a_kk + 0][a_i] = av.x;
        As[a_kk + 1][a_i] = av.y;
        As[a_kk + 2][a_i] = av.z;
        As[a_kk + 3][a_i] = av.w;
        {
            int kk = tid >> 4, col = (tid & 15) * 4;
            int k = k0 + kk;
            const float* srcp = (k < 384) ? &Wrel[(size_t)k * EDIM + col]
                                          : &Wroot[(size_t)(k - 384) * EDIM + col];
            *(float4*)&Bs[kk][col] = *(const float4*)srcp;
        }
        __syncthreads();
#pragma unroll
        for (int kk = 0; kk < 16; kk++) {
            float4 ta = *(float4*)&As[kk][rg * 4];
            float a4[4] = {ta.x, ta.y, ta.z, ta.w};
            float4 bb = *(float4*)&Bs[kk][cg * 4];
            float b4[4] = {bb.x, bb.y, bb.z, bb.w};
#pragma unroll
            for (int m = 0; m < 4; m++)
#pragma unroll
                for (int n = 0; n < 4; n++) acc[m][n] += a4[m] * b4[n];
        }
        __syncthreads();
    }
    float4 bv = *(const float4*)&bias[cg * 4];
#pragma unroll
    for (int m = 0; m < 4; m++) {
        int row = row0 + rg * 4 + m;
        if (row < M) {
            float4 o;
            o.x = acc[m][0] + bv.x;
            o.y = acc[m][1] + bv.y;
            o.z = acc[m][2] + bv.z;
            o.w = acc[m][3] + bv.w;
            *(float4*)&g_node[(size_t)row * EDIM + cg * 4] = o;
        }
    }
}

// ---------------- k8: out = tanh([node[nest]|node[food]] @ fc_W + fc_b) ------
__global__ void k8_final(const int* __restrict__ nest, const int* __restrict__ food,
                         const float* __restrict__ fcW, const float* __restrict__ fcb,
                         float* __restrict__ out) {
    __shared__ float pr[128];
    int b = blockIdx.x;
    int h = threadIdx.x;    // 0..127
    if (h < 64) {
        int tn = g_tid[nest[b]];
        pr[h] = g_node[tn * EDIM + h];
    } else {
        int tf = g_tid[food[b]];
        pr[h] = g_node[tf * EDIM + (h - 64)];
    }
    __syncthreads();
    float acc = fcb[h];
#pragma unroll 8
    for (int k = 0; k < 128; k++) acc = fmaf(pr[k], fcW[k * HDIM + h], acc);
    out[(size_t)b * HDIM + h] = tanhf(acc);
}

// ---------------- launch ----------------
extern "C" void kernel_launch(void* const* d_in, const int* in_sizes, int n_in,
                              void* d_out, int out_size) {
    const float* x      = (const float*)d_in[0];
    const int*   esrc   = (const int*)d_in[1];
    const int*   edst   = (const int*)d_in[2];
    const int*   etyp   = (const int*)d_in[3];
    // d_in[4] = edge_attr (unused by the reference output)
    const int*   nest   = (const int*)d_in[5];
    const int*   food   = (const int*)d_in[6];
    const float* Wrel1  = (const float*)d_in[7];
    const float* Wroot1 = (const float*)d_in[8];
    const float* b1     = (const float*)d_in[9];
    const float* Wrel2  = (const float*)d_in[10];
    const float* Wroot2 = (const float*)d_in[11];
    const float* b2     = (const float*)d_in[12];
    const float* fcW    = (const float*)d_in[13];
    const float* fcb    = (const float*)d_in[14];
    float* out = (float*)d_out;

    int N = in_sizes[0] / FDIM;
    int E = in_sizes[1];
    int B = in_sizes[5];

    k0_init<<<1024, 256>>>(N);
    k1_targets<<<(2 * B + 255) / 256, 256>>>(nest, food, B);
    k2_scan<<<(E + 255) / 256, 256>>>(esrc, edst, etyp, E);
    {
        dim3 g(2048, 3, 1);
        k3_zero<<<g, 256>>>();
    }
    k4_agg1<<<4736, 256>>>(esrc, edst, etyp, x, E);
    k4b_inv<<<(RREL * S1MAX + RREL * TMAXC + 255) / 256, 256>>>();
    k5_gemm_h1<<<S1MAX / 64, 256>>>(x, Wrel1, Wroot1, b1);
    k6_agg2<<<2048, 256>>>();
    k7_gemm_node<<<TMAXC / 64, 256>>>(Wrel2, Wroot2, b2);
    k8_final<<<B, 128>>>(nest, food, fcW, fcb, out);
}